// round 15
// baseline (speedup 1.0000x reference)
#include <cuda_runtime.h>
#include <cuda_fp16.h>
#include <math.h>
#include <stdint.h>

#define Bq 4
#define Nq 8192
#define Dq 1024
#define Hq 8
#define HDq 128
#define TDq 3072
#define KV_SPLIT 16

// ---------------------------------------------------------------------------
// Device scratch.
// ---------------------------------------------------------------------------
__device__ __align__(16) __half g_xh[(size_t)Bq * Nq * Dq];   // LN(x) fp16
__device__ __align__(16) __half g_wth[(size_t)TDq * Dq];      // W^T fp16 [3072,1024]
__device__ __align__(16) __half g_q[(size_t)Bq * Nq * Dq];    // sigmoid(q)
__device__ __align__(16) __half g_k[(size_t)Bq * Nq * Dq];    // tanh(k)*mask
__device__ __align__(16) __half g_v[(size_t)Bq * Nq * Dq];    // v
__device__ __align__(16) float g_kv[(size_t)Bq * Hq * HDq * HDq];
__device__ float g_maskf[(size_t)Bq * Nq];

// ---------------------------------------------------------------------------
// PTX helpers (sm_80-level; tcgen05 rejected by base compute_103, per R4).
// ---------------------------------------------------------------------------
__device__ __forceinline__ uint32_t smem_u32(const void* p) {
    uint32_t a;
    asm("{ .reg .u64 t; cvta.to.shared.u64 t, %1; cvt.u32.u64 %0, t; }" : "=r"(a) : "l"(p));
    return a;
}
#define CP_ASYNC16(saddr, gptr) \
    asm volatile("cp.async.cg.shared.global [%0], [%1], 16;" :: "r"(saddr), "l"(gptr))
#define CP_COMMIT() asm volatile("cp.async.commit_group;" ::: "memory")
#define CP_WAIT(n)  asm volatile("cp.async.wait_group %0;" :: "n"(n) : "memory")

#define LDSM4(R0, R1, R2, R3, addr) \
    asm volatile("ldmatrix.sync.aligned.m8n8.x4.shared.b16 {%0,%1,%2,%3}, [%4];" \
                 : "=r"(R0), "=r"(R1), "=r"(R2), "=r"(R3) : "r"(addr))
#define LDSM4T(R0, R1, R2, R3, addr) \
    asm volatile("ldmatrix.sync.aligned.m8n8.x4.trans.shared.b16 {%0,%1,%2,%3}, [%4];" \
                 : "=r"(R0), "=r"(R1), "=r"(R2), "=r"(R3) : "r"(addr))

#define MMAF16(d, a0, a1, a2, a3, b0, b1) \
    asm volatile("mma.sync.aligned.m16n8k16.row.col.f32.f16.f16.f32 " \
                 "{%0,%1,%2,%3}, {%4,%5,%6,%7}, {%8,%9}, {%0,%1,%2,%3};" \
                 : "+f"((d)[0]), "+f"((d)[1]), "+f"((d)[2]), "+f"((d)[3]) \
                 : "r"(a0), "r"(a1), "r"(a2), "r"(a3), "r"(b0), "r"(b1))

__device__ __forceinline__ uint32_t swz(int r, int u) {
    return (uint32_t)(r * 128 + ((u ^ (r & 7)) << 4));
}
__device__ __forceinline__ uint32_t swz256(int r, int u) {
    return (uint32_t)(r * 256 + ((u ^ ((r & 7) << 1)) << 4));
}

__device__ __forceinline__ void hsplit(float v, __half& h, __half& l) {
    h = __float2half_rn(v);
    l = __float2half_rn(v - __half2float(h));
}

// ---------------------------------------------------------------------------
// Kernel 0: mask dtype detect + canonicalize + zero kv (fused).
// ---------------------------------------------------------------------------
__global__ void mask_zero(const int* __restrict__ m) {
    __shared__ int bad;
    if (threadIdx.x == 0) bad = 0;
    __syncthreads();
    int mybad = 0;
    for (int i = threadIdx.x; i < 4096; i += 256) {
        const int v = m[i];
        if (v != 0 && v != 1) mybad = 1;
    }
    if (mybad) atomicOr(&bad, 1);
    __syncthreads();
    const int is_i32 = !bad;

    const int gid = blockIdx.x * 256 + threadIdx.x;
    const int gsz = gridDim.x * 256;
    for (int i = gid; i < Bq * Nq; i += gsz) {
        int set;
        if (is_i32) set = m[i] != 0;
        else        set = ((const unsigned char*)m)[i] != 0;
        g_maskf[i] = set ? 0.0f : 1.0f;
    }
    for (int i = gid; i < Bq * Hq * HDq * HDq; i += gsz) g_kv[i] = 0.f;
}

// ---------------------------------------------------------------------------
// Kernel 1: W [1024,3072] fp32 -> W^T [3072,1024] fp16.
// ---------------------------------------------------------------------------
__global__ void w_split(const float* __restrict__ W) {
    __shared__ float tile[32][33];
    const int n0 = blockIdx.x * 32;
    const int k0 = blockIdx.y * 32;
    const int tx = threadIdx.x, ty = threadIdx.y;
    #pragma unroll
    for (int j = 0; j < 4; j++)
        tile[ty + 8 * j][tx] = W[(size_t)(k0 + ty + 8 * j) * TDq + n0 + tx];
    __syncthreads();
    #pragma unroll
    for (int j = 0; j < 4; j++) {
        const float v = tile[tx][ty + 8 * j];
        g_wth[(size_t)(n0 + ty + 8 * j) * Dq + k0 + tx] = __float2half_rn(v);
    }
}

// ---------------------------------------------------------------------------
// Kernel 2: LayerNorm -> fp16.
// ---------------------------------------------------------------------------
__global__ void ln_split(const float* __restrict__ x,
                         const float* __restrict__ gamma,
                         const float* __restrict__ beta) {
    const int row = blockIdx.x;
    const int t = threadIdx.x;
    const float4 a = reinterpret_cast<const float4*>(x + (size_t)row * Dq)[t];
    float s  = a.x + a.y + a.z + a.w;
    float ss = a.x * a.x + a.y * a.y + a.z * a.z + a.w * a.w;

    __shared__ float red[16];
    __shared__ float mv[2];
    #pragma unroll
    for (int o = 16; o > 0; o >>= 1) {
        s  += __shfl_down_sync(0xffffffffu, s, o);
        ss += __shfl_down_sync(0xffffffffu, ss, o);
    }
    const int w = t >> 5, l = t & 31;
    if (l == 0) { red[w] = s; red[w + 8] = ss; }
    __syncthreads();
    if (t == 0) {
        float ts = 0.f, tss = 0.f;
        #pragma unroll
        for (int i = 0; i < 8; i++) { ts += red[i]; tss += red[i + 8]; }
        const float mean = ts * (1.0f / Dq);
        const float var  = tss * (1.0f / Dq) - mean * mean;
        mv[0] = mean;
        mv[1] = rsqrtf(var + 1e-5f);
    }
    __syncthreads();
    const float mean = mv[0], rstd = mv[1];
    const float4 g4 = reinterpret_cast<const float4*>(gamma)[t];
    const float4 b4 = reinterpret_cast<const float4*>(beta)[t];
    const float o0 = (a.x - mean) * rstd * g4.x + b4.x;
    const float o1 = (a.y - mean) * rstd * g4.y + b4.y;
    const float o2 = (a.z - mean) * rstd * g4.z + b4.z;
    const float o3 = (a.w - mean) * rstd * g4.w + b4.w;
    const size_t idx = (size_t)row * Dq + t * 4;
    *reinterpret_cast<__half2*>(g_xh + idx) =
        __halves2half2(__float2half_rn(o0), __float2half_rn(o1));
    *reinterpret_cast<__half2*>(g_xh + idx + 2) =
        __halves2half2(__float2half_rn(o2), __float2half_rn(o3));
}

// ---------------------------------------------------------------------------
// Kernel 3: HMMA QKV GEMM, 128x384 tile, 384 threads (12 warps, 2m x 6n),
// each warp 64x64 (min smem re-read: A x6 + B x2, 128B/MMA), 3-stage ring.
// ---------------------------------------------------------------------------
#define AT_B     16384                 // A tile: 128 rows * 128B
#define BT_B     49152                 // B tile: 384 rows * 128B
#define STAGE_B  (AT_B + BT_B)         // 64KB
#define NSTAGE   3
#define QKV_SMEM (NSTAGE * STAGE_B)    // 192KB

__global__ __launch_bounds__(384, 1) void mma_qkv_gemm() {
    extern __shared__ char smem[];
    const uint32_t su = smem_u32(smem);
    const int tid = threadIdx.x;
    const int lane = tid & 31;
    const int wid = tid >> 5;            // 0..11
    const int warp_m = wid & 1;          // 64 rows each
    const int warp_n = wid >> 1;         // 0..5 -> 64 cols each
    const int row0 = blockIdx.y * 128;
    const int col0 = blockIdx.x * 384;

    const char* gsrcA = (const char*)g_xh  + (size_t)row0 * 2048;
    const char* gsrcB = (const char*)g_wth + (size_t)col0 * 2048;

    auto load_stage = [&](int s, int c) {
        const uint32_t sb = su + s * STAGE_B;
        const size_t kb = (size_t)c * 128;
        #pragma unroll
        for (int i = 0; i < 3; ++i) {        // A: 1024 16B units
            const int w = tid + i * 384;
            if (w < 1024) {
                const int r = w >> 3;
                const int u = w & 7;
                CP_ASYNC16(sb + swz(r, u), gsrcA + (size_t)r * 2048 + kb + (size_t)u * 16);
            }
        }
        #pragma unroll
        for (int i = 0; i < 8; ++i) {        // B: 3072 16B units
            const int w = tid + i * 384;
            const int r = w >> 3;
            const int u = w & 7;
            CP_ASYNC16(sb + AT_B + swz(r, u), gsrcB + (size_t)r * 2048 + kb + (size_t)u * 16);
        }
    };

    float acc[4][8][4];
    #pragma unroll
    for (int mt = 0; mt < 4; mt++)
        #pragma unroll
        for (int nt = 0; nt < 8; nt++)
            #pragma unroll
            for (int k = 0; k < 4; k++) acc[mt][nt][k] = 0.f;

    load_stage(0, 0); CP_COMMIT();
    load_stage(1, 1); CP_COMMIT();

    for (int c = 0; c < 16; ++c) {
        if (c + 2 < 16) {
            load_stage((c + 2) % NSTAGE, c + 2); CP_COMMIT();
            CP_WAIT(2);
        } else if (c + 1 < 16) {
            CP_WAIT(1);
        } else {
            CP_WAIT(0);
        }
        __syncthreads();

        const uint32_t sb = su + (c % NSTAGE) * STAGE_B;
        #pragma unroll
        for (int kk = 0; kk < 4; ++kk) {
            uint32_t ah[4][4];
            #pragma unroll
            for (int mt = 0; mt < 4; ++mt) {
                const int r = warp_m * 64 + mt * 16 + (lane & 15);
                const int u = kk * 2 + (lane >> 4);
                LDSM4(ah[mt][0], ah[mt][1], ah[mt][2], ah[mt][3], sb + swz(r, u));
            }
            #pragma unroll
            for (int p = 0; p < 4; ++p) {
                uint32_t bh0, bh1, bh2, bh3;
                const int rn = warp_n * 64 + p * 16 + (lane & 7) + ((lane >> 4) & 1) * 8;
                const int u = kk * 2 + ((lane >> 3) & 1);
                LDSM4(bh0, bh1, bh2, bh3, sb + AT_B + swz(rn, u));
                #pragma unroll
                for (int mt = 0; mt < 4; ++mt) {
                    MMAF16(acc[mt][2 * p],     ah[mt][0], ah[mt][1], ah[mt][2], ah[mt][3], bh0, bh1);
                    MMAF16(acc[mt][2 * p + 1], ah[mt][0], ah[mt][1], ah[mt][2], ah[mt][3], bh2, bh3);
                }
            }
        }
        __syncthreads();
    }

    // epilogue: activation; q, k, v all single fp16.
    // 64-col warp group starts at a multiple of 64 -> never crosses a section
    // boundary (multiples of 1024): sec is warp-uniform.
    const int wcol = col0 + warp_n * 64;
    const int sec = wcol >> 10;          // 0=q, 1=k, 2=v
    __half* dst = (sec == 0) ? g_q : (sec == 1) ? g_k : g_v;
    const int csec0 = wcol - sec * Dq;   // column within the section
    #pragma unroll
    for (int mt = 0; mt < 4; ++mt) {
        const int r0 = row0 + warp_m * 64 + mt * 16 + (lane >> 2);
        const int r1 = r0 + 8;
        const float m0 = (sec == 1) ? g_maskf[r0] : 1.0f;
        const float m1 = (sec == 1) ? g_maskf[r1] : 1.0f;
        #pragma unroll
        for (int nt = 0; nt < 8; ++nt) {
            const int cc = csec0 + nt * 8 + (lane & 3) * 2;
            float v0 = acc[mt][nt][0], v1 = acc[mt][nt][1];
            float v2 = acc[mt][nt][2], v3 = acc[mt][nt][3];
            if (sec == 0) {
                v0 = 1.0f / (1.0f + expf(-v0));
                v1 = 1.0f / (1.0f + expf(-v1));
                v2 = 1.0f / (1.0f + expf(-v2));
                v3 = 1.0f / (1.0f + expf(-v3));
            } else if (sec == 1) {
                v0 = tanhf(v0) * m0;
                v1 = tanhf(v1) * m0;
                v2 = tanhf(v2) * m1;
                v3 = tanhf(v3) * m1;
            }
            *reinterpret_cast<__half2*>(dst + (size_t)r0 * Dq + cc) =
                __halves2half2(__float2half_rn(v0), __float2half_rn(v1));
            *reinterpret_cast<__half2*>(dst + (size_t)r1 * Dq + cc) =
                __halves2half2(__float2half_rn(v2), __float2half_rn(v3));
        }
    }
}

// ---------------------------------------------------------------------------
// Kernel 4: kv[d][e] = sum_n k[n][d] v[n][e].  HMMA 1-term, trans loads,
// 3-stage ring with R8-validated prefetch-2 schedule.
// ---------------------------------------------------------------------------
#define KVT_B    8192           // 32 rows * 256B
#define KVSTG_B  (2 * KVT_B)    // k, v
#define KV_SMEM  (3 * KVSTG_B)  // 48KB

__global__ __launch_bounds__(256, 2) void mma_kv_gemm() {
    extern __shared__ char smem[];
    const uint32_t su = smem_u32(smem);
    const int tid = threadIdx.x;
    const int lane = tid & 31;
    const int wid = tid >> 5;
    const int warp_m = wid & 3;          // d tile: 32 rows
    const int warp_n = wid >> 2;         // e tile: 64 cols
    const int bh = blockIdx.x;           // 0..31
    const int split = blockIdx.y;        // 0..15
    const int b = bh >> 3, h = bh & 7;
    const int n0 = split * (Nq / KV_SPLIT);

    const char* gk = (const char*)g_k + ((size_t)(b * Nq + n0) * Dq + h * HDq) * 2;
    const char* gv = (const char*)g_v + ((size_t)(b * Nq + n0) * Dq + h * HDq) * 2;

    auto load_stage = [&](int s, int c) {
        const uint32_t sb = su + s * KVSTG_B;
        #pragma unroll
        for (int i = 0; i < 2; ++i) {
            const int w = tid + i * 256;     // 0..511 = 32 rows * 16 units
            const int r = w >> 4;
            const int u = w & 15;
            const uint32_t so = swz256(r, u);
            const size_t go = (size_t)(c * 32 + r) * 2048 + (size_t)u * 16;
            CP_ASYNC16(sb + 0 * KVT_B + so, gk + go);
            CP_ASYNC16(sb + 1 * KVT_B + so, gv + go);
        }
    };

    float acc[2][8][4];
    #pragma unroll
    for (int mt = 0; mt < 2; mt++)
        #pragma unroll
        for (int nt = 0; nt < 8; nt++)
            #pragma unroll
            for (int k = 0; k < 4; k++) acc[mt][nt][k] = 0.f;

    load_stage(0, 0); CP_COMMIT();
    load_stage(1, 1); CP_COMMIT();

    const int NC = 16;                   // 512 n / 32
    for (int c = 0; c < NC; ++c) {
        if (c + 2 < NC) {
            load_stage((c + 2) % 3, c + 2); CP_COMMIT();
            CP_WAIT(2);
        } else if (c + 1 < NC) {
            CP_WAIT(1);
        } else {
            CP_WAIT(0);
        }
        __syncthreads();

        const uint32_t sb = su + (c % 3) * KVSTG_B;
        #pragma unroll
        for (int kk = 0; kk < 2; ++kk) {       // 2 x 16 n per stage
            uint32_t ah[2][4];
            #pragma unroll
            for (int mt = 0; mt < 2; ++mt) {
                const int m0 = warp_m * 32 + mt * 16;          // d
                const int kr = kk * 16 + (lane & 7) + ((lane >> 4) & 1) * 8;   // n row
                const int mu = (m0 >> 3) + ((lane >> 3) & 1);  // 16B unit along d
                const uint32_t so = swz256(kr, mu);
                LDSM4T(ah[mt][0], ah[mt][1], ah[mt][2], ah[mt][3], sb + 0 * KVT_B + so);
            }
            #pragma unroll
            for (int p = 0; p < 4; ++p) {
                const int e0 = warp_n * 64 + p * 16;
                const int kr = kk * 16 + (lane & 7) + ((lane >> 3) & 1) * 8;
                const int eu = (e0 >> 3) + ((lane >> 4) & 1);
                const uint32_t so = swz256(kr, eu);
                uint32_t bh0, bh1, bh2, bh3;
                LDSM4T(bh0, bh1, bh2, bh3, sb + 1 * KVT_B + so);
                #pragma unroll
                for (int mt = 0; mt < 2; ++mt) {
                    MMAF16(acc[mt][2 * p],     ah[mt][0], ah[mt][1], ah[mt][2], ah[mt][3], bh0, bh1);
                    MMAF16(acc[mt][2 * p + 1], ah[mt][0], ah[mt][1], ah[mt][2], ah[mt][3], bh2, bh3);
                }
            }
        }
        __syncthreads();
    }

    float* outp = g_kv + (size_t)bh * HDq * HDq;
    #pragma unroll
    for (int mt = 0; mt < 2; ++mt) {
        const int d0 = warp_m * 32 + mt * 16 + (lane >> 2);
        const int d1 = d0 + 8;
        #pragma unroll
        for (int nt = 0; nt < 8; ++nt) {
            const int e = warp_n * 64 + nt * 8 + (lane & 3) * 2;
            atomicAdd(&outp[d0 * HDq + e],     acc[mt][nt][0]);
            atomicAdd(&outp[d0 * HDq + e + 1], acc[mt][nt][1]);
            atomicAdd(&outp[d1 * HDq + e],     acc[mt][nt][2]);
            atomicAdd(&outp[d1 * HDq + e + 1], acc[mt][nt][3]);
        }
    }
}

// ---------------------------------------------------------------------------
// Kernel 5: out[n][e] = sum_d q[n][d] kv[d][e].  HMMA 2-term (q@kvh + q@kvl).
// 512 rows per CTA: kv converted once, 4 q-tiles ping-pong through 2 buffers.
// ---------------------------------------------------------------------------
#define OUT_QT_B  (128 * 256)          // 32KB per q tile
#define OUT_SMEM  (4 * OUT_QT_B)       // 128KB: q buf0, q buf1, kvh, kvl

__global__ __launch_bounds__(256, 1) void mma_out_gemm(float* __restrict__ out) {
    extern __shared__ char smem[];
    const uint32_t su = smem_u32(smem);
    const int tid = threadIdx.x;
    const int lane = tid & 31;
    const int wid = tid >> 5;
    const int warp_m = wid & 3;
    const int warp_n = wid >> 2;
    const int n0 = blockIdx.x * 512;
    const int bh = blockIdx.y;
    const int b = bh >> 3, h = bh & 7;

    const char* gq = (const char*)g_q + ((size_t)(b * Nq + n0) * Dq + h * HDq) * 2;

    auto load_q_tile = [&](int t, int buf) {   // tile t rows -> buffer buf
        const uint32_t sb = su + buf * OUT_QT_B;
        const char* src = gq + (size_t)t * 128 * 2048;
        #pragma unroll
        for (int i = 0; i < 8; ++i) {
            const int w = tid + i * 256;     // 0..2047 = 128 rows * 16 units
            const int r = w >> 4;
            const int u = w & 15;
            CP_ASYNC16(sb + swz256(r, u), src + (size_t)r * 2048 + (size_t)u * 16);
        }
    };

    auto compute_tile = [&](int t, int buf) {
        const uint32_t qb = su + buf * OUT_QT_B;
        float acc[2][8][4];
        #pragma unroll
        for (int mt = 0; mt < 2; mt++)
            #pragma unroll
            for (int nt = 0; nt < 8; nt++)
                #pragma unroll
                for (int k = 0; k < 4; k++) acc[mt][nt][k] = 0.f;

        #pragma unroll
        for (int kk = 0; kk < 8; ++kk) {         // K = d = 128
            uint32_t ah[2][4];
            #pragma unroll
            for (int mt = 0; mt < 2; ++mt) {
                const int r = warp_m * 32 + mt * 16 + (lane & 15);
                const int u = kk * 2 + (lane >> 4);
                LDSM4(ah[mt][0], ah[mt][1], ah[mt][2], ah[mt][3], qb + swz256(r, u));
            }
            #pragma unroll
            for (int p = 0; p < 4; ++p) {
                const int e0 = warp_n * 64 + p * 16;
                const int kr = kk * 16 + (lane & 7) + ((lane >> 3) & 1) * 8;   // d row
                const int eu = (e0 >> 3) + ((lane >> 4) & 1);
                const uint32_t so = swz256(kr, eu);
                uint32_t bh0, bh1, bh2, bh3, bl0, bl1, bl2, bl3;
                LDSM4T(bh0, bh1, bh2, bh3, su + 2 * OUT_QT_B + so);
                LDSM4T(bl0, bl1, bl2, bl3, su + 3 * OUT_QT_B + so);
                #pragma unroll
                for (int mt = 0; mt < 2; ++mt) {
                    MMAF16(acc[mt][2 * p],     ah[mt][0], ah[mt][1], ah[mt][2], ah[mt][3], bh0, bh1);
                    MMAF16(acc[mt][2 * p + 1], ah[mt][0], ah[mt][1], ah[mt][2], ah[mt][3], bh2, bh3);
                    MMAF16(acc[mt][2 * p],     ah[mt][0], ah[mt][1], ah[mt][2], ah[mt][3], bl0, bl1);
                    MMAF16(acc[mt][2 * p + 1], ah[mt][0], ah[mt][1], ah[mt][2], ah[mt][3], bl2, bl3);
                }
            }
        }

        #pragma unroll
        for (int mt = 0; mt < 2; ++mt) {
            const int r0 = n0 + t * 128 + warp_m * 32 + mt * 16 + (lane >> 2);
            const int r1 = r0 + 8;
            #pragma unroll
            for (int nt = 0; nt < 8; ++nt) {
                const int e = warp_n * 64 + nt * 8 + (lane & 3) * 2;
                float* o0 = out + (size_t)(b * Nq + r0) * Dq + h * HDq + e;
                float* o1 = out + (size_t)(b * Nq + r1) * Dq + h * HDq + e;
                *reinterpret_cast<float2*>(o0) = make_float2(acc[mt][nt][0], acc[mt][nt][1]);
                *reinterpret_cast<float2*>(o1) = make_float2(acc[mt][nt][2], acc[mt][nt][3]);
            }
        }
    };

    load_q_tile(0, 0); CP_COMMIT();

    // convert kv f32 -> fp16 hi/lo into swizzled smem (once per CTA)
    {
        const float* kvp = g_kv + (size_t)bh * HDq * HDq;
        __half* s_kvh = (__half*)(smem + 2 * OUT_QT_B);
        __half* s_kvl = (__half*)(smem + 3 * OUT_QT_B);
        #pragma unroll
        for (int i = 0; i < 64; ++i) {
            const int idx = tid + i * 256;   // 0..16383
            const int d = idx >> 7, e = idx & 127;
            const float v = kvp[idx];
            __half hh, hl;
            hsplit(v, hh, hl);
            const uint32_t off = swz256(d, e >> 3) + (e & 7) * 2;
            *reinterpret_cast<__half*>((char*)s_kvh + off) = hh;
            *reinterpret_cast<__half*>((char*)s_kvl + off) = hl;
        }
    }
    load_q_tile(1, 1); CP_COMMIT();

    CP_WAIT(1); __syncthreads();      // q0 + kv conversion visible
    compute_tile(0, 0);
    __syncthreads();                  // buf0 free
    load_q_tile(2, 0); CP_COMMIT();
    CP_WAIT(1); __syncthreads();      // q1 landed
    compute_tile(1, 1);
    __syncthreads();                  // buf1 free
    load_q_tile(3, 1); CP_COMMIT();
    CP_WAIT(1); __syncthreads();      // q2 landed
    compute_tile(2, 0);
    CP_WAIT(0); __syncthreads();      // q3 landed
    compute_tile(3, 1);
}

// ---------------------------------------------------------------------------
// Launch: inputs in metadata order: x, mask, w_qkv, gamma, beta.
// mma_qkv_gemm stays at launch index 3 (ncu capture target).
// ---------------------------------------------------------------------------
extern "C" void kernel_launch(void* const* d_in, const int* in_sizes, int n_in,
                              void* d_out, int out_size) {
    const float* x     = (const float*)d_in[0];
    const void*  mask  = d_in[1];
    const float* w     = (const float*)d_in[2];
    const float* gamma = (const float*)d_in[3];
    const float* beta  = (const float*)d_in[4];
    float* out         = (float*)d_out;

    static int smem_set = 0;
    if (!smem_set) {
        cudaFuncSetAttribute(mma_qkv_gemm, cudaFuncAttributeMaxDynamicSharedMemorySize, QKV_SMEM);
        cudaFuncSetAttribute(mma_kv_gemm,  cudaFuncAttributeMaxDynamicSharedMemorySize, KV_SMEM);
        cudaFuncSetAttribute(mma_out_gemm, cudaFuncAttributeMaxDynamicSharedMemorySize, OUT_SMEM);
        smem_set = 1;
    }

    mask_zero<<<256, 256>>>((const int*)mask);
    w_split<<<dim3(TDq / 32, Dq / 32), dim3(32, 8)>>>(w);
    ln_split<<<Bq * Nq, 256>>>(x, gamma, beta);
    mma_qkv_gemm<<<dim3(TDq / 384, (Bq * Nq) / 128), 384, QKV_SMEM>>>();
    mma_kv_gemm<<<dim3(Bq * Hq, KV_SPLIT), 256, KV_SMEM>>>();
    mma_out_gemm<<<dim3(Nq / 512, Bq * Hq), 256, OUT_SMEM>>>(out);
}

// round 16
// speedup vs baseline: 1.1135x; 1.1135x over previous
#include <cuda_runtime.h>
#include <cuda_fp16.h>
#include <math.h>
#include <stdint.h>

#define Bq 4
#define Nq 8192
#define Dq 1024
#define Hq 8
#define HDq 128
#define TDq 3072
#define KV_SPLIT 16

// ---------------------------------------------------------------------------
// Device scratch.
// ---------------------------------------------------------------------------
__device__ __align__(16) __half g_xh[(size_t)Bq * Nq * Dq];   // LN(x) fp16
__device__ __align__(16) __half g_wth[(size_t)TDq * Dq];      // W^T fp16 [3072,1024]
__device__ __align__(16) __half g_q[(size_t)Bq * Nq * Dq];    // sigmoid(q)
__device__ __align__(16) __half g_k[(size_t)Bq * Nq * Dq];    // tanh(k)*mask
__device__ __align__(16) __half g_v[(size_t)Bq * Nq * Dq];    // v
__device__ __align__(16) float g_kv[(size_t)Bq * Hq * HDq * HDq];
__device__ float g_maskf[(size_t)Bq * Nq];

// ---------------------------------------------------------------------------
// PTX helpers (sm_80-level; tcgen05 rejected by base compute_103, per R4).
// ---------------------------------------------------------------------------
__device__ __forceinline__ uint32_t smem_u32(const void* p) {
    uint32_t a;
    asm("{ .reg .u64 t; cvta.to.shared.u64 t, %1; cvt.u32.u64 %0, t; }" : "=r"(a) : "l"(p));
    return a;
}
#define CP_ASYNC16(saddr, gptr) \
    asm volatile("cp.async.cg.shared.global [%0], [%1], 16;" :: "r"(saddr), "l"(gptr))
#define CP_COMMIT() asm volatile("cp.async.commit_group;" ::: "memory")
#define CP_WAIT(n)  asm volatile("cp.async.wait_group %0;" :: "n"(n) : "memory")

#define LDSM4(R0, R1, R2, R3, addr) \
    asm volatile("ldmatrix.sync.aligned.m8n8.x4.shared.b16 {%0,%1,%2,%3}, [%4];" \
                 : "=r"(R0), "=r"(R1), "=r"(R2), "=r"(R3) : "r"(addr))
#define LDSM4T(R0, R1, R2, R3, addr) \
    asm volatile("ldmatrix.sync.aligned.m8n8.x4.trans.shared.b16 {%0,%1,%2,%3}, [%4];" \
                 : "=r"(R0), "=r"(R1), "=r"(R2), "=r"(R3) : "r"(addr))

#define MMAF16(d, a0, a1, a2, a3, b0, b1) \
    asm volatile("mma.sync.aligned.m16n8k16.row.col.f32.f16.f16.f32 " \
                 "{%0,%1,%2,%3}, {%4,%5,%6,%7}, {%8,%9}, {%0,%1,%2,%3};" \
                 : "+f"((d)[0]), "+f"((d)[1]), "+f"((d)[2]), "+f"((d)[3]) \
                 : "r"(a0), "r"(a1), "r"(a2), "r"(a3), "r"(b0), "r"(b1))

__device__ __forceinline__ uint32_t swz(int r, int u) {
    return (uint32_t)(r * 128 + ((u ^ (r & 7)) << 4));
}
__device__ __forceinline__ uint32_t swz256(int r, int u) {
    return (uint32_t)(r * 256 + ((u ^ ((r & 7) << 1)) << 4));
}

__device__ __forceinline__ void hsplit(float v, __half& h, __half& l) {
    h = __float2half_rn(v);
    l = __float2half_rn(v - __half2float(h));
}

// ---------------------------------------------------------------------------
// Kernel 0: mask dtype detect + canonicalize + zero kv (fused).
// ---------------------------------------------------------------------------
__global__ void mask_zero(const int* __restrict__ m) {
    __shared__ int bad;
    if (threadIdx.x == 0) bad = 0;
    __syncthreads();
    int mybad = 0;
    for (int i = threadIdx.x; i < 4096; i += 256) {
        const int v = m[i];
        if (v != 0 && v != 1) mybad = 1;
    }
    if (mybad) atomicOr(&bad, 1);
    __syncthreads();
    const int is_i32 = !bad;

    const int gid = blockIdx.x * 256 + threadIdx.x;
    const int gsz = gridDim.x * 256;
    for (int i = gid; i < Bq * Nq; i += gsz) {
        int set;
        if (is_i32) set = m[i] != 0;
        else        set = ((const unsigned char*)m)[i] != 0;
        g_maskf[i] = set ? 0.0f : 1.0f;
    }
    for (int i = gid; i < Bq * Hq * HDq * HDq; i += gsz) g_kv[i] = 0.f;
}

// ---------------------------------------------------------------------------
// Kernel 1: W [1024,3072] fp32 -> W^T [3072,1024] fp16.
// ---------------------------------------------------------------------------
__global__ void w_split(const float* __restrict__ W) {
    __shared__ float tile[32][33];
    const int n0 = blockIdx.x * 32;
    const int k0 = blockIdx.y * 32;
    const int tx = threadIdx.x, ty = threadIdx.y;
    #pragma unroll
    for (int j = 0; j < 4; j++)
        tile[ty + 8 * j][tx] = W[(size_t)(k0 + ty + 8 * j) * TDq + n0 + tx];
    __syncthreads();
    #pragma unroll
    for (int j = 0; j < 4; j++) {
        const float v = tile[tx][ty + 8 * j];
        g_wth[(size_t)(n0 + ty + 8 * j) * Dq + k0 + tx] = __float2half_rn(v);
    }
}

// ---------------------------------------------------------------------------
// Kernel 2: LayerNorm -> fp16.
// ---------------------------------------------------------------------------
__global__ void ln_split(const float* __restrict__ x,
                         const float* __restrict__ gamma,
                         const float* __restrict__ beta) {
    const int row = blockIdx.x;
    const int t = threadIdx.x;
    const float4 a = reinterpret_cast<const float4*>(x + (size_t)row * Dq)[t];
    float s  = a.x + a.y + a.z + a.w;
    float ss = a.x * a.x + a.y * a.y + a.z * a.z + a.w * a.w;

    __shared__ float red[16];
    __shared__ float mv[2];
    #pragma unroll
    for (int o = 16; o > 0; o >>= 1) {
        s  += __shfl_down_sync(0xffffffffu, s, o);
        ss += __shfl_down_sync(0xffffffffu, ss, o);
    }
    const int w = t >> 5, l = t & 31;
    if (l == 0) { red[w] = s; red[w + 8] = ss; }
    __syncthreads();
    if (t == 0) {
        float ts = 0.f, tss = 0.f;
        #pragma unroll
        for (int i = 0; i < 8; i++) { ts += red[i]; tss += red[i + 8]; }
        const float mean = ts * (1.0f / Dq);
        const float var  = tss * (1.0f / Dq) - mean * mean;
        mv[0] = mean;
        mv[1] = rsqrtf(var + 1e-5f);
    }
    __syncthreads();
    const float mean = mv[0], rstd = mv[1];
    const float4 g4 = reinterpret_cast<const float4*>(gamma)[t];
    const float4 b4 = reinterpret_cast<const float4*>(beta)[t];
    const float o0 = (a.x - mean) * rstd * g4.x + b4.x;
    const float o1 = (a.y - mean) * rstd * g4.y + b4.y;
    const float o2 = (a.z - mean) * rstd * g4.z + b4.z;
    const float o3 = (a.w - mean) * rstd * g4.w + b4.w;
    const size_t idx = (size_t)row * Dq + t * 4;
    *reinterpret_cast<__half2*>(g_xh + idx) =
        __halves2half2(__float2half_rn(o0), __float2half_rn(o1));
    *reinterpret_cast<__half2*>(g_xh + idx + 2) =
        __halves2half2(__float2half_rn(o2), __float2half_rn(o3));
}

// ---------------------------------------------------------------------------
// Kernel 3: HMMA QKV GEMM, 128x256 tile, 512 threads (16 warps, 4m x 4n),
// 4-stage pipeline with SINGLE barrier per chunk (wait -> barrier -> prefetch
// -> compute; WAR on stage (c+3)%4 covered by the same barrier).
// ---------------------------------------------------------------------------
#define AT_B     16384                 // A tile: 128 rows * 128B
#define BT_B     32768                 // B tile: 256 rows * 128B
#define STAGE_B  (AT_B + BT_B)         // 48KB
#define NSTAGE   4
#define QKV_SMEM (NSTAGE * STAGE_B)    // 192KB

__global__ __launch_bounds__(512, 1) void mma_qkv_gemm() {
    extern __shared__ char smem[];
    const uint32_t su = smem_u32(smem);
    const int tid = threadIdx.x;
    const int lane = tid & 31;
    const int wid = tid >> 5;            // 0..15
    const int warp_m = wid & 3;          // 32 rows each
    const int warp_n = wid >> 2;         // 0..3 -> 64 cols each
    const int row0 = blockIdx.y * 128;
    const int col0 = blockIdx.x * 256;

    const char* gsrcA = (const char*)g_xh  + (size_t)row0 * 2048;
    const char* gsrcB = (const char*)g_wth + (size_t)col0 * 2048;

    auto load_stage = [&](int s, int c) {
        const uint32_t sb = su + s * STAGE_B;
        const size_t kb = (size_t)c * 128;
        #pragma unroll
        for (int i = 0; i < 2; ++i) {        // A: 1024 16B units
            const int w = tid + i * 512;
            const int r = w >> 3;
            const int u = w & 7;
            CP_ASYNC16(sb + swz(r, u), gsrcA + (size_t)r * 2048 + kb + (size_t)u * 16);
        }
        #pragma unroll
        for (int i = 0; i < 4; ++i) {        // B: 2048 16B units
            const int w = tid + i * 512;
            const int r = w >> 3;
            const int u = w & 7;
            CP_ASYNC16(sb + AT_B + swz(r, u), gsrcB + (size_t)r * 2048 + kb + (size_t)u * 16);
        }
    };

    float acc[2][8][4];
    #pragma unroll
    for (int mt = 0; mt < 2; mt++)
        #pragma unroll
        for (int nt = 0; nt < 8; nt++)
            #pragma unroll
            for (int k = 0; k < 4; k++) acc[mt][nt][k] = 0.f;

    load_stage(0, 0); CP_COMMIT();
    load_stage(1, 1); CP_COMMIT();
    load_stage(2, 2); CP_COMMIT();

    for (int c = 0; c < 16; ++c) {
        // groups issued so far: up to c+2 -> wait until <=2 pending => group c done
        if (c < 14)      { CP_WAIT(2); }
        else if (c < 15) { CP_WAIT(1); }
        else             { CP_WAIT(0); }
        __syncthreads();      // everyone's copies of stage c visible; all warps
                              // past compute c-1 => safe to overwrite (c+3)%4
        if (c + 3 < 16) { load_stage((c + 3) % NSTAGE, c + 3); CP_COMMIT(); }

        const uint32_t sb = su + (c % NSTAGE) * STAGE_B;
        #pragma unroll
        for (int kk = 0; kk < 4; ++kk) {
            uint32_t ah[2][4];
            #pragma unroll
            for (int mt = 0; mt < 2; ++mt) {
                const int r = warp_m * 32 + mt * 16 + (lane & 15);
                const int u = kk * 2 + (lane >> 4);
                LDSM4(ah[mt][0], ah[mt][1], ah[mt][2], ah[mt][3], sb + swz(r, u));
            }
            #pragma unroll
            for (int p = 0; p < 4; ++p) {
                uint32_t bh0, bh1, bh2, bh3;
                const int rn = warp_n * 64 + p * 16 + (lane & 7) + ((lane >> 4) & 1) * 8;
                const int u = kk * 2 + ((lane >> 3) & 1);
                LDSM4(bh0, bh1, bh2, bh3, sb + AT_B + swz(rn, u));
                #pragma unroll
                for (int mt = 0; mt < 2; ++mt) {
                    MMAF16(acc[mt][2 * p],     ah[mt][0], ah[mt][1], ah[mt][2], ah[mt][3], bh0, bh1);
                    MMAF16(acc[mt][2 * p + 1], ah[mt][0], ah[mt][1], ah[mt][2], ah[mt][3], bh2, bh3);
                }
            }
        }
    }

    // epilogue: activation; q, k, v all single fp16.
    const int sec = blockIdx.x >> 2;     // 4 x 256-wide blocks per section
    __half* dst = (sec == 0) ? g_q : (sec == 1) ? g_k : g_v;
    const int csec0 = col0 - sec * Dq;   // column within the section [0,1024)
    #pragma unroll
    for (int mt = 0; mt < 2; ++mt) {
        const int r0 = row0 + warp_m * 32 + mt * 16 + (lane >> 2);
        const int r1 = r0 + 8;
        const float m0 = (sec == 1) ? g_maskf[r0] : 1.0f;
        const float m1 = (sec == 1) ? g_maskf[r1] : 1.0f;
        #pragma unroll
        for (int nt = 0; nt < 8; ++nt) {
            const int cc = csec0 + warp_n * 64 + nt * 8 + (lane & 3) * 2;
            float v0 = acc[mt][nt][0], v1 = acc[mt][nt][1];
            float v2 = acc[mt][nt][2], v3 = acc[mt][nt][3];
            if (sec == 0) {
                v0 = 1.0f / (1.0f + expf(-v0));
                v1 = 1.0f / (1.0f + expf(-v1));
                v2 = 1.0f / (1.0f + expf(-v2));
                v3 = 1.0f / (1.0f + expf(-v3));
            } else if (sec == 1) {
                v0 = tanhf(v0) * m0;
                v1 = tanhf(v1) * m0;
                v2 = tanhf(v2) * m1;
                v3 = tanhf(v3) * m1;
            }
            *reinterpret_cast<__half2*>(dst + (size_t)r0 * Dq + cc) =
                __halves2half2(__float2half_rn(v0), __float2half_rn(v1));
            *reinterpret_cast<__half2*>(dst + (size_t)r1 * Dq + cc) =
                __halves2half2(__float2half_rn(v2), __float2half_rn(v3));
        }
    }
}

// ---------------------------------------------------------------------------
// Kernel 4: kv[d][e] = sum_n k[n][d] v[n][e].  HMMA 1-term, trans loads,
// 3-stage ring with R8-validated prefetch-2 schedule.
// ---------------------------------------------------------------------------
#define KVT_B    8192           // 32 rows * 256B
#define KVSTG_B  (2 * KVT_B)    // k, v
#define KV_SMEM  (3 * KVSTG_B)  // 48KB

__global__ __launch_bounds__(256, 2) void mma_kv_gemm() {
    extern __shared__ char smem[];
    const uint32_t su = smem_u32(smem);
    const int tid = threadIdx.x;
    const int lane = tid & 31;
    const int wid = tid >> 5;
    const int warp_m = wid & 3;          // d tile: 32 rows
    const int warp_n = wid >> 2;         // e tile: 64 cols
    const int bh = blockIdx.x;           // 0..31
    const int split = blockIdx.y;        // 0..15
    const int b = bh >> 3, h = bh & 7;
    const int n0 = split * (Nq / KV_SPLIT);

    const char* gk = (const char*)g_k + ((size_t)(b * Nq + n0) * Dq + h * HDq) * 2;
    const char* gv = (const char*)g_v + ((size_t)(b * Nq + n0) * Dq + h * HDq) * 2;

    auto load_stage = [&](int s, int c) {
        const uint32_t sb = su + s * KVSTG_B;
        #pragma unroll
        for (int i = 0; i < 2; ++i) {
            const int w = tid + i * 256;     // 0..511 = 32 rows * 16 units
            const int r = w >> 4;
            const int u = w & 15;
            const uint32_t so = swz256(r, u);
            const size_t go = (size_t)(c * 32 + r) * 2048 + (size_t)u * 16;
            CP_ASYNC16(sb + 0 * KVT_B + so, gk + go);
            CP_ASYNC16(sb + 1 * KVT_B + so, gv + go);
        }
    };

    float acc[2][8][4];
    #pragma unroll
    for (int mt = 0; mt < 2; mt++)
        #pragma unroll
        for (int nt = 0; nt < 8; nt++)
            #pragma unroll
            for (int k = 0; k < 4; k++) acc[mt][nt][k] = 0.f;

    load_stage(0, 0); CP_COMMIT();
    load_stage(1, 1); CP_COMMIT();

    const int NC = 16;                   // 512 n / 32
    for (int c = 0; c < NC; ++c) {
        if (c + 2 < NC) {
            load_stage((c + 2) % 3, c + 2); CP_COMMIT();
            CP_WAIT(2);
        } else if (c + 1 < NC) {
            CP_WAIT(1);
        } else {
            CP_WAIT(0);
        }
        __syncthreads();

        const uint32_t sb = su + (c % 3) * KVSTG_B;
        #pragma unroll
        for (int kk = 0; kk < 2; ++kk) {       // 2 x 16 n per stage
            uint32_t ah[2][4];
            #pragma unroll
            for (int mt = 0; mt < 2; ++mt) {
                const int m0 = warp_m * 32 + mt * 16;          // d
                const int kr = kk * 16 + (lane & 7) + ((lane >> 4) & 1) * 8;   // n row
                const int mu = (m0 >> 3) + ((lane >> 3) & 1);  // 16B unit along d
                const uint32_t so = swz256(kr, mu);
                LDSM4T(ah[mt][0], ah[mt][1], ah[mt][2], ah[mt][3], sb + 0 * KVT_B + so);
            }
            #pragma unroll
            for (int p = 0; p < 4; ++p) {
                const int e0 = warp_n * 64 + p * 16;
                const int kr = kk * 16 + (lane & 7) + ((lane >> 3) & 1) * 8;
                const int eu = (e0 >> 3) + ((lane >> 4) & 1);
                const uint32_t so = swz256(kr, eu);
                uint32_t bh0, bh1, bh2, bh3;
                LDSM4T(bh0, bh1, bh2, bh3, sb + 1 * KVT_B + so);
                #pragma unroll
                for (int mt = 0; mt < 2; ++mt) {
                    MMAF16(acc[mt][2 * p],     ah[mt][0], ah[mt][1], ah[mt][2], ah[mt][3], bh0, bh1);
                    MMAF16(acc[mt][2 * p + 1], ah[mt][0], ah[mt][1], ah[mt][2], ah[mt][3], bh2, bh3);
                }
            }
        }
        __syncthreads();
    }

    float* outp = g_kv + (size_t)bh * HDq * HDq;
    #pragma unroll
    for (int mt = 0; mt < 2; ++mt) {
        const int d0 = warp_m * 32 + mt * 16 + (lane >> 2);
        const int d1 = d0 + 8;
        #pragma unroll
        for (int nt = 0; nt < 8; ++nt) {
            const int e = warp_n * 64 + nt * 8 + (lane & 3) * 2;
            atomicAdd(&outp[d0 * HDq + e],     acc[mt][nt][0]);
            atomicAdd(&outp[d0 * HDq + e + 1], acc[mt][nt][1]);
            atomicAdd(&outp[d1 * HDq + e],     acc[mt][nt][2]);
            atomicAdd(&outp[d1 * HDq + e + 1], acc[mt][nt][3]);
        }
    }
}

// ---------------------------------------------------------------------------
// Kernel 5: out[n][e] = sum_d q[n][d] kv[d][e].  HMMA 2-term (q@kvh + q@kvl).
// 512 rows per CTA: kv converted once, 4 q-tiles ping-pong through 2 buffers.
// ---------------------------------------------------------------------------
#define OUT_QT_B  (128 * 256)          // 32KB per q tile
#define OUT_SMEM  (4 * OUT_QT_B)       // 128KB: q buf0, q buf1, kvh, kvl

__global__ __launch_bounds__(256, 1) void mma_out_gemm(float* __restrict__ out) {
    extern __shared__ char smem[];
    const uint32_t su = smem_u32(smem);
    const int tid = threadIdx.x;
    const int lane = tid & 31;
    const int wid = tid >> 5;
    const int warp_m = wid & 3;
    const int warp_n = wid >> 2;
    const int n0 = blockIdx.x * 512;
    const int bh = blockIdx.y;
    const int b = bh >> 3, h = bh & 7;

    const char* gq = (const char*)g_q + ((size_t)(b * Nq + n0) * Dq + h * HDq) * 2;

    auto load_q_tile = [&](int t, int buf) {   // tile t rows -> buffer buf
        const uint32_t sb = su + buf * OUT_QT_B;
        const char* src = gq + (size_t)t * 128 * 2048;
        #pragma unroll
        for (int i = 0; i < 8; ++i) {
            const int w = tid + i * 256;     // 0..2047 = 128 rows * 16 units
            const int r = w >> 4;
            const int u = w & 15;
            CP_ASYNC16(sb + swz256(r, u), src + (size_t)r * 2048 + (size_t)u * 16);
        }
    };

    auto compute_tile = [&](int t, int buf) {
        const uint32_t qb = su + buf * OUT_QT_B;
        float acc[2][8][4];
        #pragma unroll
        for (int mt = 0; mt < 2; mt++)
            #pragma unroll
            for (int nt = 0; nt < 8; nt++)
                #pragma unroll
                for (int k = 0; k < 4; k++) acc[mt][nt][k] = 0.f;

        #pragma unroll
        for (int kk = 0; kk < 8; ++kk) {         // K = d = 128
            uint32_t ah[2][4];
            #pragma unroll
            for (int mt = 0; mt < 2; ++mt) {
                const int r = warp_m * 32 + mt * 16 + (lane & 15);
                const int u = kk * 2 + (lane >> 4);
                LDSM4(ah[mt][0], ah[mt][1], ah[mt][2], ah[mt][3], qb + swz256(r, u));
            }
            #pragma unroll
            for (int p = 0; p < 4; ++p) {
                const int e0 = warp_n * 64 + p * 16;
                const int kr = kk * 16 + (lane & 7) + ((lane >> 3) & 1) * 8;   // d row
                const int eu = (e0 >> 3) + ((lane >> 4) & 1);
                const uint32_t so = swz256(kr, eu);
                uint32_t bh0, bh1, bh2, bh3, bl0, bl1, bl2, bl3;
                LDSM4T(bh0, bh1, bh2, bh3, su + 2 * OUT_QT_B + so);
                LDSM4T(bl0, bl1, bl2, bl3, su + 3 * OUT_QT_B + so);
                #pragma unroll
                for (int mt = 0; mt < 2; ++mt) {
                    MMAF16(acc[mt][2 * p],     ah[mt][0], ah[mt][1], ah[mt][2], ah[mt][3], bh0, bh1);
                    MMAF16(acc[mt][2 * p + 1], ah[mt][0], ah[mt][1], ah[mt][2], ah[mt][3], bh2, bh3);
                    MMAF16(acc[mt][2 * p],     ah[mt][0], ah[mt][1], ah[mt][2], ah[mt][3], bl0, bl1);
                    MMAF16(acc[mt][2 * p + 1], ah[mt][0], ah[mt][1], ah[mt][2], ah[mt][3], bl2, bl3);
                }
            }
        }

        #pragma unroll
        for (int mt = 0; mt < 2; ++mt) {
            const int r0 = n0 + t * 128 + warp_m * 32 + mt * 16 + (lane >> 2);
            const int r1 = r0 + 8;
            #pragma unroll
            for (int nt = 0; nt < 8; ++nt) {
                const int e = warp_n * 64 + nt * 8 + (lane & 3) * 2;
                float* o0 = out + (size_t)(b * Nq + r0) * Dq + h * HDq + e;
                float* o1 = out + (size_t)(b * Nq + r1) * Dq + h * HDq + e;
                *reinterpret_cast<float2*>(o0) = make_float2(acc[mt][nt][0], acc[mt][nt][1]);
                *reinterpret_cast<float2*>(o1) = make_float2(acc[mt][nt][2], acc[mt][nt][3]);
            }
        }
    };

    load_q_tile(0, 0); CP_COMMIT();

    // convert kv f32 -> fp16 hi/lo into swizzled smem (once per CTA)
    {
        const float* kvp = g_kv + (size_t)bh * HDq * HDq;
        __half* s_kvh = (__half*)(smem + 2 * OUT_QT_B);
        __half* s_kvl = (__half*)(smem + 3 * OUT_QT_B);
        #pragma unroll
        for (int i = 0; i < 64; ++i) {
            const int idx = tid + i * 256;   // 0..16383
            const int d = idx >> 7, e = idx & 127;
            const float v = kvp[idx];
            __half hh, hl;
            hsplit(v, hh, hl);
            const uint32_t off = swz256(d, e >> 3) + (e & 7) * 2;
            *reinterpret_cast<__half*>((char*)s_kvh + off) = hh;
            *reinterpret_cast<__half*>((char*)s_kvl + off) = hl;
        }
    }
    load_q_tile(1, 1); CP_COMMIT();

    CP_WAIT(1); __syncthreads();      // q0 + kv conversion visible
    compute_tile(0, 0);
    __syncthreads();                  // buf0 free
    load_q_tile(2, 0); CP_COMMIT();
    CP_WAIT(1); __syncthreads();      // q1 landed
    compute_tile(1, 1);
    __syncthreads();                  // buf1 free
    load_q_tile(3, 1); CP_COMMIT();
    CP_WAIT(1); __syncthreads();      // q2 landed
    compute_tile(2, 0);
    CP_WAIT(0); __syncthreads();      // q3 landed
    compute_tile(3, 1);
}

// ---------------------------------------------------------------------------
// Launch: inputs in metadata order: x, mask, w_qkv, gamma, beta.
// mma_qkv_gemm stays at launch index 3 (ncu capture target).
// ---------------------------------------------------------------------------
extern "C" void kernel_launch(void* const* d_in, const int* in_sizes, int n_in,
                              void* d_out, int out_size) {
    const float* x     = (const float*)d_in[0];
    const void*  mask  = d_in[1];
    const float* w     = (const float*)d_in[2];
    const float* gamma = (const float*)d_in[3];
    const float* beta  = (const float*)d_in[4];
    float* out         = (float*)d_out;

    static int smem_set = 0;
    if (!smem_set) {
        cudaFuncSetAttribute(mma_qkv_gemm, cudaFuncAttributeMaxDynamicSharedMemorySize, QKV_SMEM);
        cudaFuncSetAttribute(mma_kv_gemm,  cudaFuncAttributeMaxDynamicSharedMemorySize, KV_SMEM);
        cudaFuncSetAttribute(mma_out_gemm, cudaFuncAttributeMaxDynamicSharedMemorySize, OUT_SMEM);
        smem_set = 1;
    }

    mask_zero<<<256, 256>>>((const int*)mask);
    w_split<<<dim3(TDq / 32, Dq / 32), dim3(32, 8)>>>(w);
    ln_split<<<Bq * Nq, 256>>>(x, gamma, beta);
    mma_qkv_gemm<<<dim3(TDq / 256, (Bq * Nq) / 128), 512, QKV_SMEM>>>();
    mma_kv_gemm<<<dim3(Bq * Hq, KV_SPLIT), 256, KV_SMEM>>>();
    mma_out_gemm<<<dim3(Nq / 512, Bq * Hq), 256, OUT_SMEM>>>(out);
}

// round 17
// speedup vs baseline: 1.2070x; 1.0839x over previous
#include <cuda_runtime.h>
#include <cuda_fp16.h>
#include <math.h>
#include <stdint.h>

#define Bq 4
#define Nq 8192
#define Dq 1024
#define Hq 8
#define HDq 128
#define TDq 3072
#define KV_SPLIT 16

// ---------------------------------------------------------------------------
// Device scratch.
// ---------------------------------------------------------------------------
__device__ __align__(16) __half g_xh[(size_t)Bq * Nq * Dq];   // LN(x) fp16
__device__ __align__(16) __half g_wth[(size_t)TDq * Dq];      // W^T fp16 [3072,1024]
__device__ __align__(16) __half g_q[(size_t)Bq * Nq * Dq];    // sigmoid(q)
__device__ __align__(16) __half g_k[(size_t)Bq * Nq * Dq];    // tanh(k)*mask
__device__ __align__(16) __half g_v[(size_t)Bq * Nq * Dq];    // v
__device__ __align__(16) float g_kv[(size_t)Bq * Hq * HDq * HDq];
__device__ float g_maskf[(size_t)Bq * Nq];

// ---------------------------------------------------------------------------
// PTX helpers (sm_80-level; tcgen05 rejected by base compute_103, per R4).
// ---------------------------------------------------------------------------
__device__ __forceinline__ uint32_t smem_u32(const void* p) {
    uint32_t a;
    asm("{ .reg .u64 t; cvta.to.shared.u64 t, %1; cvt.u32.u64 %0, t; }" : "=r"(a) : "l"(p));
    return a;
}
#define CP_ASYNC16(saddr, gptr) \
    asm volatile("cp.async.cg.shared.global [%0], [%1], 16;" :: "r"(saddr), "l"(gptr))
#define CP_COMMIT() asm volatile("cp.async.commit_group;" ::: "memory")
#define CP_WAIT(n)  asm volatile("cp.async.wait_group %0;" :: "n"(n) : "memory")

#define LDSM4(R0, R1, R2, R3, addr) \
    asm volatile("ldmatrix.sync.aligned.m8n8.x4.shared.b16 {%0,%1,%2,%3}, [%4];" \
                 : "=r"(R0), "=r"(R1), "=r"(R2), "=r"(R3) : "r"(addr))
#define LDSM4T(R0, R1, R2, R3, addr) \
    asm volatile("ldmatrix.sync.aligned.m8n8.x4.trans.shared.b16 {%0,%1,%2,%3}, [%4];" \
                 : "=r"(R0), "=r"(R1), "=r"(R2), "=r"(R3) : "r"(addr))

#define MMAF16(d, a0, a1, a2, a3, b0, b1) \
    asm volatile("mma.sync.aligned.m16n8k16.row.col.f32.f16.f16.f32 " \
                 "{%0,%1,%2,%3}, {%4,%5,%6,%7}, {%8,%9}, {%0,%1,%2,%3};" \
                 : "+f"((d)[0]), "+f"((d)[1]), "+f"((d)[2]), "+f"((d)[3]) \
                 : "r"(a0), "r"(a1), "r"(a2), "r"(a3), "r"(b0), "r"(b1))

__device__ __forceinline__ uint32_t swz(int r, int u) {
    return (uint32_t)(r * 128 + ((u ^ (r & 7)) << 4));
}
__device__ __forceinline__ uint32_t swz256(int r, int u) {
    return (uint32_t)(r * 256 + ((u ^ ((r & 7) << 1)) << 4));
}

__device__ __forceinline__ void hsplit(float v, __half& h, __half& l) {
    h = __float2half_rn(v);
    l = __float2half_rn(v - __half2float(h));
}

// ---------------------------------------------------------------------------
// Kernel 0: mask dtype detect + canonicalize + zero kv (fused).
// ---------------------------------------------------------------------------
__global__ void mask_zero(const int* __restrict__ m) {
    __shared__ int bad;
    if (threadIdx.x == 0) bad = 0;
    __syncthreads();
    int mybad = 0;
    for (int i = threadIdx.x; i < 4096; i += 256) {
        const int v = m[i];
        if (v != 0 && v != 1) mybad = 1;
    }
    if (mybad) atomicOr(&bad, 1);
    __syncthreads();
    const int is_i32 = !bad;

    const int gid = blockIdx.x * 256 + threadIdx.x;
    const int gsz = gridDim.x * 256;
    for (int i = gid; i < Bq * Nq; i += gsz) {
        int set;
        if (is_i32) set = m[i] != 0;
        else        set = ((const unsigned char*)m)[i] != 0;
        g_maskf[i] = set ? 0.0f : 1.0f;
    }
    for (int i = gid; i < Bq * Hq * HDq * HDq; i += gsz) g_kv[i] = 0.f;
}

// ---------------------------------------------------------------------------
// Kernel 1: W [1024,3072] fp32 -> W^T [3072,1024] fp16.
// ---------------------------------------------------------------------------
__global__ void w_split(const float* __restrict__ W) {
    __shared__ float tile[32][33];
    const int n0 = blockIdx.x * 32;
    const int k0 = blockIdx.y * 32;
    const int tx = threadIdx.x, ty = threadIdx.y;
    #pragma unroll
    for (int j = 0; j < 4; j++)
        tile[ty + 8 * j][tx] = W[(size_t)(k0 + ty + 8 * j) * TDq + n0 + tx];
    __syncthreads();
    #pragma unroll
    for (int j = 0; j < 4; j++) {
        const float v = tile[tx][ty + 8 * j];
        g_wth[(size_t)(n0 + ty + 8 * j) * Dq + k0 + tx] = __float2half_rn(v);
    }
}

// ---------------------------------------------------------------------------
// Kernel 2: LayerNorm -> fp16.
// ---------------------------------------------------------------------------
__global__ void ln_split(const float* __restrict__ x,
                         const float* __restrict__ gamma,
                         const float* __restrict__ beta) {
    const int row = blockIdx.x;
    const int t = threadIdx.x;
    const float4 a = reinterpret_cast<const float4*>(x + (size_t)row * Dq)[t];
    float s  = a.x + a.y + a.z + a.w;
    float ss = a.x * a.x + a.y * a.y + a.z * a.z + a.w * a.w;

    __shared__ float red[16];
    __shared__ float mv[2];
    #pragma unroll
    for (int o = 16; o > 0; o >>= 1) {
        s  += __shfl_down_sync(0xffffffffu, s, o);
        ss += __shfl_down_sync(0xffffffffu, ss, o);
    }
    const int w = t >> 5, l = t & 31;
    if (l == 0) { red[w] = s; red[w + 8] = ss; }
    __syncthreads();
    if (t == 0) {
        float ts = 0.f, tss = 0.f;
        #pragma unroll
        for (int i = 0; i < 8; i++) { ts += red[i]; tss += red[i + 8]; }
        const float mean = ts * (1.0f / Dq);
        const float var  = tss * (1.0f / Dq) - mean * mean;
        mv[0] = mean;
        mv[1] = rsqrtf(var + 1e-5f);
    }
    __syncthreads();
    const float mean = mv[0], rstd = mv[1];
    const float4 g4 = reinterpret_cast<const float4*>(gamma)[t];
    const float4 b4 = reinterpret_cast<const float4*>(beta)[t];
    const float o0 = (a.x - mean) * rstd * g4.x + b4.x;
    const float o1 = (a.y - mean) * rstd * g4.y + b4.y;
    const float o2 = (a.z - mean) * rstd * g4.z + b4.z;
    const float o3 = (a.w - mean) * rstd * g4.w + b4.w;
    const size_t idx = (size_t)row * Dq + t * 4;
    *reinterpret_cast<__half2*>(g_xh + idx) =
        __halves2half2(__float2half_rn(o0), __float2half_rn(o1));
    *reinterpret_cast<__half2*>(g_xh + idx + 2) =
        __halves2half2(__float2half_rn(o2), __float2half_rn(o3));
}

// ---------------------------------------------------------------------------
// Kernel 3: HMMA QKV GEMM, 128x128 tile, 256 threads (8 warps, 4m x 2n),
// 3-stage ring, 96KB smem -> 2 CTAs/SM (two independent pipeline domains).
// Single barrier per chunk (wait -> barrier -> prefetch c+2 -> compute).
// ---------------------------------------------------------------------------
#define AT_B     16384                 // A tile: 128 rows * 128B
#define BT_B     16384                 // B tile: 128 rows * 128B
#define STAGE_B  (AT_B + BT_B)         // 32KB
#define NSTAGE   3
#define QKV_SMEM (NSTAGE * STAGE_B)    // 96KB -> 2 CTAs/SM

__global__ __launch_bounds__(256, 2) void mma_qkv_gemm() {
    extern __shared__ char smem[];
    const uint32_t su = smem_u32(smem);
    const int tid = threadIdx.x;
    const int lane = tid & 31;
    const int wid = tid >> 5;            // 0..7
    const int warp_m = wid & 3;          // 32 rows each
    const int warp_n = wid >> 2;         // 0..1 -> 64 cols each
    const int row0 = blockIdx.y * 128;
    const int col0 = blockIdx.x * 128;

    const char* gsrcA = (const char*)g_xh  + (size_t)row0 * 2048;
    const char* gsrcB = (const char*)g_wth + (size_t)col0 * 2048;

    auto load_stage = [&](int s, int c) {
        const uint32_t sb = su + s * STAGE_B;
        const size_t kb = (size_t)c * 128;
        #pragma unroll
        for (int i = 0; i < 4; ++i) {        // A: 1024 16B units
            const int w = tid + i * 256;
            const int r = w >> 3;
            const int u = w & 7;
            CP_ASYNC16(sb + swz(r, u), gsrcA + (size_t)r * 2048 + kb + (size_t)u * 16);
        }
        #pragma unroll
        for (int i = 0; i < 4; ++i) {        // B: 1024 16B units
            const int w = tid + i * 256;
            const int r = w >> 3;
            const int u = w & 7;
            CP_ASYNC16(sb + AT_B + swz(r, u), gsrcB + (size_t)r * 2048 + kb + (size_t)u * 16);
        }
    };

    float acc[2][8][4];
    #pragma unroll
    for (int mt = 0; mt < 2; mt++)
        #pragma unroll
        for (int nt = 0; nt < 8; nt++)
            #pragma unroll
            for (int k = 0; k < 4; k++) acc[mt][nt][k] = 0.f;

    load_stage(0, 0); CP_COMMIT();
    load_stage(1, 1); CP_COMMIT();

    for (int c = 0; c < 16; ++c) {
        // groups issued so far: up to c+1 -> wait until <=1 pending => group c done
        if (c < 15) { CP_WAIT(1); }
        else        { CP_WAIT(0); }
        __syncthreads();      // stage c visible to all; all warps past compute
                              // c-1 => safe to overwrite (c+2)%3 below
        if (c + 2 < 16) { load_stage((c + 2) % NSTAGE, c + 2); CP_COMMIT(); }

        const uint32_t sb = su + (c % NSTAGE) * STAGE_B;
        #pragma unroll
        for (int kk = 0; kk < 4; ++kk) {
            uint32_t ah[2][4];
            #pragma unroll
            for (int mt = 0; mt < 2; ++mt) {
                const int r = warp_m * 32 + mt * 16 + (lane & 15);
                const int u = kk * 2 + (lane >> 4);
                LDSM4(ah[mt][0], ah[mt][1], ah[mt][2], ah[mt][3], sb + swz(r, u));
            }
            #pragma unroll
            for (int p = 0; p < 4; ++p) {
                uint32_t bh0, bh1, bh2, bh3;
                const int rn = warp_n * 64 + p * 16 + (lane & 7) + ((lane >> 4) & 1) * 8;
                const int u = kk * 2 + ((lane >> 3) & 1);
                LDSM4(bh0, bh1, bh2, bh3, sb + AT_B + swz(rn, u));
                #pragma unroll
                for (int mt = 0; mt < 2; ++mt) {
                    MMAF16(acc[mt][2 * p],     ah[mt][0], ah[mt][1], ah[mt][2], ah[mt][3], bh0, bh1);
                    MMAF16(acc[mt][2 * p + 1], ah[mt][0], ah[mt][1], ah[mt][2], ah[mt][3], bh2, bh3);
                }
            }
        }
    }

    // epilogue: activation; q, k, v all single fp16.
    const int sec = blockIdx.x >> 3;     // 8 x 128-wide blocks per section
    __half* dst = (sec == 0) ? g_q : (sec == 1) ? g_k : g_v;
    const int csec0 = col0 - sec * Dq;   // column within the section [0,1024)
    #pragma unroll
    for (int mt = 0; mt < 2; ++mt) {
        const int r0 = row0 + warp_m * 32 + mt * 16 + (lane >> 2);
        const int r1 = r0 + 8;
        const float m0 = (sec == 1) ? g_maskf[r0] : 1.0f;
        const float m1 = (sec == 1) ? g_maskf[r1] : 1.0f;
        #pragma unroll
        for (int nt = 0; nt < 8; ++nt) {
            const int cc = csec0 + warp_n * 64 + nt * 8 + (lane & 3) * 2;
            float v0 = acc[mt][nt][0], v1 = acc[mt][nt][1];
            float v2 = acc[mt][nt][2], v3 = acc[mt][nt][3];
            if (sec == 0) {
                v0 = 1.0f / (1.0f + expf(-v0));
                v1 = 1.0f / (1.0f + expf(-v1));
                v2 = 1.0f / (1.0f + expf(-v2));
                v3 = 1.0f / (1.0f + expf(-v3));
            } else if (sec == 1) {
                v0 = tanhf(v0) * m0;
                v1 = tanhf(v1) * m0;
                v2 = tanhf(v2) * m1;
                v3 = tanhf(v3) * m1;
            }
            *reinterpret_cast<__half2*>(dst + (size_t)r0 * Dq + cc) =
                __halves2half2(__float2half_rn(v0), __float2half_rn(v1));
            *reinterpret_cast<__half2*>(dst + (size_t)r1 * Dq + cc) =
                __halves2half2(__float2half_rn(v2), __float2half_rn(v3));
        }
    }
}

// ---------------------------------------------------------------------------
// Kernel 4: kv[d][e] = sum_n k[n][d] v[n][e].  HMMA 1-term, trans loads,
// 3-stage ring with R8-validated prefetch-2 schedule.
// ---------------------------------------------------------------------------
#define KVT_B    8192           // 32 rows * 256B
#define KVSTG_B  (2 * KVT_B)    // k, v
#define KV_SMEM  (3 * KVSTG_B)  // 48KB

__global__ __launch_bounds__(256, 2) void mma_kv_gemm() {
    extern __shared__ char smem[];
    const uint32_t su = smem_u32(smem);
    const int tid = threadIdx.x;
    const int lane = tid & 31;
    const int wid = tid >> 5;
    const int warp_m = wid & 3;          // d tile: 32 rows
    const int warp_n = wid >> 2;         // e tile: 64 cols
    const int bh = blockIdx.x;           // 0..31
    const int split = blockIdx.y;        // 0..15
    const int b = bh >> 3, h = bh & 7;
    const int n0 = split * (Nq / KV_SPLIT);

    const char* gk = (const char*)g_k + ((size_t)(b * Nq + n0) * Dq + h * HDq) * 2;
    const char* gv = (const char*)g_v + ((size_t)(b * Nq + n0) * Dq + h * HDq) * 2;

    auto load_stage = [&](int s, int c) {
        const uint32_t sb = su + s * KVSTG_B;
        #pragma unroll
        for (int i = 0; i < 2; ++i) {
            const int w = tid + i * 256;     // 0..511 = 32 rows * 16 units
            const int r = w >> 4;
            const int u = w & 15;
            const uint32_t so = swz256(r, u);
            const size_t go = (size_t)(c * 32 + r) * 2048 + (size_t)u * 16;
            CP_ASYNC16(sb + 0 * KVT_B + so, gk + go);
            CP_ASYNC16(sb + 1 * KVT_B + so, gv + go);
        }
    };

    float acc[2][8][4];
    #pragma unroll
    for (int mt = 0; mt < 2; mt++)
        #pragma unroll
        for (int nt = 0; nt < 8; nt++)
            #pragma unroll
            for (int k = 0; k < 4; k++) acc[mt][nt][k] = 0.f;

    load_stage(0, 0); CP_COMMIT();
    load_stage(1, 1); CP_COMMIT();

    const int NC = 16;                   // 512 n / 32
    for (int c = 0; c < NC; ++c) {
        if (c + 2 < NC) {
            load_stage((c + 2) % 3, c + 2); CP_COMMIT();
            CP_WAIT(2);
        } else if (c + 1 < NC) {
            CP_WAIT(1);
        } else {
            CP_WAIT(0);
        }
        __syncthreads();

        const uint32_t sb = su + (c % 3) * KVSTG_B;
        #pragma unroll
        for (int kk = 0; kk < 2; ++kk) {       // 2 x 16 n per stage
            uint32_t ah[2][4];
            #pragma unroll
            for (int mt = 0; mt < 2; ++mt) {
                const int m0 = warp_m * 32 + mt * 16;          // d
                const int kr = kk * 16 + (lane & 7) + ((lane >> 4) & 1) * 8;   // n row
                const int mu = (m0 >> 3) + ((lane >> 3) & 1);  // 16B unit along d
                const uint32_t so = swz256(kr, mu);
                LDSM4T(ah[mt][0], ah[mt][1], ah[mt][2], ah[mt][3], sb + 0 * KVT_B + so);
            }
            #pragma unroll
            for (int p = 0; p < 4; ++p) {
                const int e0 = warp_n * 64 + p * 16;
                const int kr = kk * 16 + (lane & 7) + ((lane >> 3) & 1) * 8;
                const int eu = (e0 >> 3) + ((lane >> 4) & 1);
                const uint32_t so = swz256(kr, eu);
                uint32_t bh0, bh1, bh2, bh3;
                LDSM4T(bh0, bh1, bh2, bh3, sb + 1 * KVT_B + so);
                #pragma unroll
                for (int mt = 0; mt < 2; ++mt) {
                    MMAF16(acc[mt][2 * p],     ah[mt][0], ah[mt][1], ah[mt][2], ah[mt][3], bh0, bh1);
                    MMAF16(acc[mt][2 * p + 1], ah[mt][0], ah[mt][1], ah[mt][2], ah[mt][3], bh2, bh3);
                }
            }
        }
        __syncthreads();
    }

    float* outp = g_kv + (size_t)bh * HDq * HDq;
    #pragma unroll
    for (int mt = 0; mt < 2; ++mt) {
        const int d0 = warp_m * 32 + mt * 16 + (lane >> 2);
        const int d1 = d0 + 8;
        #pragma unroll
        for (int nt = 0; nt < 8; ++nt) {
            const int e = warp_n * 64 + nt * 8 + (lane & 3) * 2;
            atomicAdd(&outp[d0 * HDq + e],     acc[mt][nt][0]);
            atomicAdd(&outp[d0 * HDq + e + 1], acc[mt][nt][1]);
            atomicAdd(&outp[d1 * HDq + e],     acc[mt][nt][2]);
            atomicAdd(&outp[d1 * HDq + e + 1], acc[mt][nt][3]);
        }
    }
}

// ---------------------------------------------------------------------------
// Kernel 5: out[n][e] = sum_d q[n][d] kv[d][e].  HMMA 2-term (q@kvh + q@kvl).
// 512 rows per CTA: kv converted once, 4 q-tiles ping-pong through 2 buffers.
// ---------------------------------------------------------------------------
#define OUT_QT_B  (128 * 256)          // 32KB per q tile
#define OUT_SMEM  (4 * OUT_QT_B)       // 128KB: q buf0, q buf1, kvh, kvl

__global__ __launch_bounds__(256, 1) void mma_out_gemm(float* __restrict__ out) {
    extern __shared__ char smem[];
    const uint32_t su = smem_u32(smem);
    const int tid = threadIdx.x;
    const int lane = tid & 31;
    const int wid = tid >> 5;
    const int warp_m = wid & 3;
    const int warp_n = wid >> 2;
    const int n0 = blockIdx.x * 512;
    const int bh = blockIdx.y;
    const int b = bh >> 3, h = bh & 7;

    const char* gq = (const char*)g_q + ((size_t)(b * Nq + n0) * Dq + h * HDq) * 2;

    auto load_q_tile = [&](int t, int buf) {   // tile t rows -> buffer buf
        const uint32_t sb = su + buf * OUT_QT_B;
        const char* src = gq + (size_t)t * 128 * 2048;
        #pragma unroll
        for (int i = 0; i < 8; ++i) {
            const int w = tid + i * 256;     // 0..2047 = 128 rows * 16 units
            const int r = w >> 4;
            const int u = w & 15;
            CP_ASYNC16(sb + swz256(r, u), src + (size_t)r * 2048 + (size_t)u * 16);
        }
    };

    auto compute_tile = [&](int t, int buf) {
        const uint32_t qb = su + buf * OUT_QT_B;
        float acc[2][8][4];
        #pragma unroll
        for (int mt = 0; mt < 2; mt++)
            #pragma unroll
            for (int nt = 0; nt < 8; nt++)
                #pragma unroll
                for (int k = 0; k < 4; k++) acc[mt][nt][k] = 0.f;

        #pragma unroll
        for (int kk = 0; kk < 8; ++kk) {         // K = d = 128
            uint32_t ah[2][4];
            #pragma unroll
            for (int mt = 0; mt < 2; ++mt) {
                const int r = warp_m * 32 + mt * 16 + (lane & 15);
                const int u = kk * 2 + (lane >> 4);
                LDSM4(ah[mt][0], ah[mt][1], ah[mt][2], ah[mt][3], qb + swz256(r, u));
            }
            #pragma unroll
            for (int p = 0; p < 4; ++p) {
                const int e0 = warp_n * 64 + p * 16;
                const int kr = kk * 16 + (lane & 7) + ((lane >> 3) & 1) * 8;   // d row
                const int eu = (e0 >> 3) + ((lane >> 4) & 1);
                const uint32_t so = swz256(kr, eu);
                uint32_t bh0, bh1, bh2, bh3, bl0, bl1, bl2, bl3;
                LDSM4T(bh0, bh1, bh2, bh3, su + 2 * OUT_QT_B + so);
                LDSM4T(bl0, bl1, bl2, bl3, su + 3 * OUT_QT_B + so);
                #pragma unroll
                for (int mt = 0; mt < 2; ++mt) {
                    MMAF16(acc[mt][2 * p],     ah[mt][0], ah[mt][1], ah[mt][2], ah[mt][3], bh0, bh1);
                    MMAF16(acc[mt][2 * p + 1], ah[mt][0], ah[mt][1], ah[mt][2], ah[mt][3], bh2, bh3);
                    MMAF16(acc[mt][2 * p],     ah[mt][0], ah[mt][1], ah[mt][2], ah[mt][3], bl0, bl1);
                    MMAF16(acc[mt][2 * p + 1], ah[mt][0], ah[mt][1], ah[mt][2], ah[mt][3], bl2, bl3);
                }
            }
        }

        #pragma unroll
        for (int mt = 0; mt < 2; ++mt) {
            const int r0 = n0 + t * 128 + warp_m * 32 + mt * 16 + (lane >> 2);
            const int r1 = r0 + 8;
            #pragma unroll
            for (int nt = 0; nt < 8; ++nt) {
                const int e = warp_n * 64 + nt * 8 + (lane & 3) * 2;
                float* o0 = out + (size_t)(b * Nq + r0) * Dq + h * HDq + e;
                float* o1 = out + (size_t)(b * Nq + r1) * Dq + h * HDq + e;
                *reinterpret_cast<float2*>(o0) = make_float2(acc[mt][nt][0], acc[mt][nt][1]);
                *reinterpret_cast<float2*>(o1) = make_float2(acc[mt][nt][2], acc[mt][nt][3]);
            }
        }
    };

    load_q_tile(0, 0); CP_COMMIT();

    // convert kv f32 -> fp16 hi/lo into swizzled smem (once per CTA)
    {
        const float* kvp = g_kv + (size_t)bh * HDq * HDq;
        __half* s_kvh = (__half*)(smem + 2 * OUT_QT_B);
        __half* s_kvl = (__half*)(smem + 3 * OUT_QT_B);
        #pragma unroll
        for (int i = 0; i < 64; ++i) {
            const int idx = tid + i * 256;   // 0..16383
            const int d = idx >> 7, e = idx & 127;
            const float v = kvp[idx];
            __half hh, hl;
            hsplit(v, hh, hl);
            const uint32_t off = swz256(d, e >> 3) + (e & 7) * 2;
            *reinterpret_cast<__half*>((char*)s_kvh + off) = hh;
            *reinterpret_cast<__half*>((char*)s_kvl + off) = hl;
        }
    }
    load_q_tile(1, 1); CP_COMMIT();

    CP_WAIT(1); __syncthreads();      // q0 + kv conversion visible
    compute_tile(0, 0);
    __syncthreads();                  // buf0 free
    load_q_tile(2, 0); CP_COMMIT();
    CP_WAIT(1); __syncthreads();      // q1 landed
    compute_tile(1, 1);
    __syncthreads();                  // buf1 free
    load_q_tile(3, 1); CP_COMMIT();
    CP_WAIT(1); __syncthreads();      // q2 landed
    compute_tile(2, 0);
    CP_WAIT(0); __syncthreads();      // q3 landed
    compute_tile(3, 1);
}

// ---------------------------------------------------------------------------
// Launch: inputs in metadata order: x, mask, w_qkv, gamma, beta.
// mma_qkv_gemm stays at launch index 3 (ncu capture target).
// ---------------------------------------------------------------------------
extern "C" void kernel_launch(void* const* d_in, const int* in_sizes, int n_in,
                              void* d_out, int out_size) {
    const float* x     = (const float*)d_in[0];
    const void*  mask  = d_in[1];
    const float* w     = (const float*)d_in[2];
    const float* gamma = (const float*)d_in[3];
    const float* beta  = (const float*)d_in[4];
    float* out         = (float*)d_out;

    static int smem_set = 0;
    if (!smem_set) {
        cudaFuncSetAttribute(mma_qkv_gemm, cudaFuncAttributeMaxDynamicSharedMemorySize, QKV_SMEM);
        cudaFuncSetAttribute(mma_kv_gemm,  cudaFuncAttributeMaxDynamicSharedMemorySize, KV_SMEM);
        cudaFuncSetAttribute(mma_out_gemm, cudaFuncAttributeMaxDynamicSharedMemorySize, OUT_SMEM);
        smem_set = 1;
    }

    mask_zero<<<256, 256>>>((const int*)mask);
    w_split<<<dim3(TDq / 32, Dq / 32), dim3(32, 8)>>>(w);
    ln_split<<<Bq * Nq, 256>>>(x, gamma, beta);
    mma_qkv_gemm<<<dim3(TDq / 128, (Bq * Nq) / 128), 256, QKV_SMEM>>>();
    mma_kv_gemm<<<dim3(Bq * Hq, KV_SPLIT), 256, KV_SMEM>>>();
    mma_out_gemm<<<dim3(Nq / 512, Bq * Hq), 256, OUT_SMEM>>>(out);
}